// round 4
// baseline (speedup 1.0000x reference)
#include <cuda_runtime.h>
#include <cstdio>
#include <cstdint>

#define B_ 2
#define S_ 2048
#define D_ 1024
#define H_ 16
#define HD_ 64

// ---------------- scratch (device globals; no allocation allowed) ----------------
__device__ float g_q[(size_t)B_ * H_ * S_ * HD_];     // [B,H,S,Hd]
__device__ float g_kT[(size_t)B_ * H_ * HD_ * S_];    // [B,H,Hd,S]
__device__ float g_v[(size_t)B_ * H_ * S_ * HD_];     // [B,H,S,Hd]
__device__ float g_attn[(size_t)B_ * S_ * D_];        // [B,S,D] (H,Hd interleaved)
__device__ float g_scores[(size_t)B_ * H_ * S_ * S_]; // fallback weights buffer

// ---------------- helpers ----------------
__device__ __forceinline__ uint32_t f2tf32(float x) {
    uint32_t u;
    asm("cvt.rna.tf32.f32 %0, %1;" : "=r"(u) : "f"(x));
    return u;
}

__device__ __forceinline__ void mma_tf32(float& c0, float& c1, float& c2, float& c3,
                                         uint32_t a0, uint32_t a1, uint32_t a2, uint32_t a3,
                                         uint32_t b0, uint32_t b1) {
    asm volatile(
        "mma.sync.aligned.m16n8k8.row.col.f32.tf32.tf32.f32 "
        "{%0,%1,%2,%3}, {%4,%5,%6,%7}, {%8,%9}, {%0,%1,%2,%3};"
        : "+f"(c0), "+f"(c1), "+f"(c2), "+f"(c3)
        : "r"(a0), "r"(a1), "r"(a2), "r"(a3), "r"(b0), "r"(b1));
}

// ---------------- epilogues ----------------
struct EpiQKV {
    const float* bias;
    __device__ __forceinline__ void operator()(int, int m, int n, float v) const {
        v += bias[n];
        int part = n >> 10;           // 0=q 1=k 2=v
        int rem = n & 1023;
        int h = rem >> 6;
        int d = rem & 63;
        int b = m >> 11;
        int s = m & 2047;
        size_t bh = (size_t)(b * H_ + h);
        if (part == 0)
            g_q[(bh * S_ + s) * HD_ + d] = v;
        else if (part == 1)
            g_kT[(bh * HD_ + d) * S_ + s] = v;
        else
            g_v[(bh * S_ + s) * HD_ + d] = v;
    }
};

struct EpiScore {
    float* dst; // [B*H, S, S]
    __device__ __forceinline__ void operator()(int bz, int m, int n, float v) const {
        dst[((size_t)bz * S_ + m) * S_ + n] = v * 0.125f; // 1/sqrt(64)
    }
};

struct EpiAV {
    __device__ __forceinline__ void operator()(int bz, int m, int n, float v) const {
        int b = bz >> 4;
        int h = bz & 15;
        g_attn[(((size_t)b * S_ + m) * H_ + h) * HD_ + n] = v;
    }
};

struct EpiOut {
    const float* bias;
    float* out;
    __device__ __forceinline__ void operator()(int, int m, int n, float v) const {
        out[(size_t)m * D_ + n] = v + bias[n];
    }
};

// ---------------- tensor-core tf32 GEMM ----------------
// C[M,N] = A[M,K](lda) @ B[K,N](ldb), batched over blockIdx.z.
// BK=32 fixed. 256 threads = 8 warps arranged (BM/WM) x (BN/WN).
// smem holds tiles in fragment-major layout:
//   A: [BM/16][4 ksteps][32 lanes][4 slots]  (slot: a0,a1,a2,a3 of m16n8k8)
//   B: [BN/8][4 ksteps][32 lanes][2 slots]   (slot: b0,b1)
template <int BM, int BN, int WM, int WN, class Epi>
__global__ void __launch_bounds__(256)
tgemm_kernel(const float* __restrict__ Aall, const float* __restrict__ Ball,
             int K, int lda, int ldb,
             long long strideA, long long strideB, Epi epi) {
    constexpr int BK = 32;
    constexpr int NWM = BM / WM;            // warps along M
    constexpr int NWN = BN / WN;            // warps along N
    static_assert(NWM * NWN == 8, "8 warps");
    constexpr int MT = WM / 16;             // m-tiles per warp
    constexpr int NT = WN / 8;              // n-tiles per warp
    constexpr int A4 = BM * BK / 4 / 256;   // float4 A loads per thread
    constexpr int B4 = BK * BN / 4 / 256;   // float4 B loads per thread
    static_assert(A4 * 256 * 4 == BM * BK, "A tile");
    static_assert(B4 * 256 * 4 == BK * BN, "B tile");

    __shared__ uint32_t sA[BM * BK];
    __shared__ uint32_t sB[BK * BN];

    const int bz = blockIdx.z;
    const float* A = Aall + (size_t)bz * strideA;
    const float* Bp = Ball + (size_t)bz * strideB;

    const int tid = threadIdx.x;
    const int lane = tid & 31;
    const int warp = tid >> 5;
    const int wm = warp / NWN;
    const int wn = warp % NWN;
    const int row0 = blockIdx.y * BM;
    const int col0 = blockIdx.x * BN;

    float acc[MT][NT][4];
#pragma unroll
    for (int i = 0; i < MT; i++)
#pragma unroll
        for (int j = 0; j < NT; j++)
#pragma unroll
            for (int v = 0; v < 4; v++) acc[i][j][v] = 0.f;

    for (int k0 = 0; k0 < K; k0 += BK) {
        // ---- stage A (scatter to fragment layout, cvt to tf32) ----
#pragma unroll
        for (int it = 0; it < A4; ++it) {
            int idx = tid + it * 256;
            int r = idx >> 3;             // row in tile (BK/4 = 8 float4 per row)
            int c4 = (idx & 7) << 2;      // col
            float4 v = *reinterpret_cast<const float4*>(
                &A[(size_t)(row0 + r) * lda + k0 + c4]);
            int mt = r >> 4, rw = r & 15;
            float vv[4] = {v.x, v.y, v.z, v.w};
#pragma unroll
            for (int j = 0; j < 4; j++) {
                int c = c4 + j;
                int ks = c >> 3, ci = c & 7;
                int ln = ((rw & 7) << 2) | (ci & 3);
                int slot = (rw >> 3) | ((ci >> 2) << 1);
                sA[((((mt << 2) + ks) << 5) + ln) * 4 + slot] = f2tf32(vv[j]);
            }
        }
        // ---- stage B ----
#pragma unroll
        for (int it = 0; it < B4; ++it) {
            int idx = tid + it * 256;
            int r = idx / (BN / 4);       // k within tile
            int c4 = (idx % (BN / 4)) << 2;
            float4 v = *reinterpret_cast<const float4*>(
                &Bp[(size_t)(k0 + r) * ldb + col0 + c4]);
            int ks = r >> 3, rw = r & 7;
            float vv[4] = {v.x, v.y, v.z, v.w};
#pragma unroll
            for (int j = 0; j < 4; j++) {
                int n = c4 + j;
                int nt = n >> 3, ci = n & 7;
                int ln = (ci << 2) | (rw & 3);
                int slot = rw >> 2;
                sB[((((nt << 2) + ks) << 5) + ln) * 2 + slot] = f2tf32(vv[j]);
            }
        }
        __syncthreads();

        // ---- compute ----
#pragma unroll
        for (int ks = 0; ks < 4; ks++) {
            uint4 af[MT];
            uint2 bf[NT];
#pragma unroll
            for (int i = 0; i < MT; i++) {
                int frag = (wm * MT + i) * 4 + ks;
                af[i] = *reinterpret_cast<const uint4*>(&sA[((frag << 5) + lane) * 4]);
            }
#pragma unroll
            for (int j = 0; j < NT; j++) {
                int frag = (wn * NT + j) * 4 + ks;
                bf[j] = *reinterpret_cast<const uint2*>(&sB[((frag << 5) + lane) * 2]);
            }
#pragma unroll
            for (int i = 0; i < MT; i++)
#pragma unroll
                for (int j = 0; j < NT; j++)
                    mma_tf32(acc[i][j][0], acc[i][j][1], acc[i][j][2], acc[i][j][3],
                             af[i].x, af[i].y, af[i].z, af[i].w, bf[j].x, bf[j].y);
        }
        __syncthreads();
    }

    // ---- epilogue ----
#pragma unroll
    for (int i = 0; i < MT; i++) {
        int m0 = row0 + wm * WM + i * 16 + (lane >> 2);
#pragma unroll
        for (int j = 0; j < NT; j++) {
            int n0 = col0 + wn * WN + j * 8 + ((lane & 3) << 1);
            epi(bz, m0, n0, acc[i][j][0]);
            epi(bz, m0, n0 + 1, acc[i][j][1]);
            epi(bz, m0 + 8, n0, acc[i][j][2]);
            epi(bz, m0 + 8, n0 + 1, acc[i][j][3]);
        }
    }
}

// ---------------- softmax: one block per row, IN-PLACE ----------------
__global__ void __launch_bounds__(256)
softmax_kernel(float* __restrict__ buf) {
    const size_t row = blockIdx.x;
    float* d = buf + row * S_;
    const int tid = threadIdx.x;

    float4 a = *reinterpret_cast<const float4*>(d + tid * 4);
    float4 b = *reinterpret_cast<const float4*>(d + 1024 + tid * 4);

    float m = fmaxf(fmaxf(fmaxf(a.x, a.y), fmaxf(a.z, a.w)),
                    fmaxf(fmaxf(b.x, b.y), fmaxf(b.z, b.w)));
#pragma unroll
    for (int o = 16; o; o >>= 1) m = fmaxf(m, __shfl_xor_sync(0xffffffffu, m, o));

    __shared__ float redm[8];
    if ((tid & 31) == 0) redm[tid >> 5] = m;
    __syncthreads();
    m = redm[0];
#pragma unroll
    for (int w = 1; w < 8; w++) m = fmaxf(m, redm[w]);

    a.x = __expf(a.x - m); a.y = __expf(a.y - m);
    a.z = __expf(a.z - m); a.w = __expf(a.w - m);
    b.x = __expf(b.x - m); b.y = __expf(b.y - m);
    b.z = __expf(b.z - m); b.w = __expf(b.w - m);

    float sum = (a.x + a.y) + (a.z + a.w) + (b.x + b.y) + (b.z + b.w);
#pragma unroll
    for (int o = 16; o; o >>= 1) sum += __shfl_xor_sync(0xffffffffu, sum, o);

    __shared__ float reds[8];
    if ((tid & 31) == 0) reds[tid >> 5] = sum;
    __syncthreads();
    sum = reds[0];
#pragma unroll
    for (int w = 1; w < 8; w++) sum += reds[w];

    float inv = 1.0f / sum;
    a.x *= inv; a.y *= inv; a.z *= inv; a.w *= inv;
    b.x *= inv; b.y *= inv; b.z *= inv; b.w *= inv;

    *reinterpret_cast<float4*>(d + tid * 4) = a;
    *reinterpret_cast<float4*>(d + 1024 + tid * 4) = b;
}

// ---------------- launch ----------------
extern "C" void kernel_launch(void* const* d_in, const int* in_sizes, int n_in,
                              void* d_out, int out_size) {
    const float* query = (const float*)d_in[0]; // [B,S,D]
    const float* W_qkv = (const float*)d_in[1]; // [D,3D]
    const float* b_qkv = (const float*)d_in[2]; // [3D]
    const float* W_out = (const float*)d_in[3]; // [D,D]
    const float* b_out = (const float*)d_in[4]; // [D]
    float* out = (float*)d_out;

    const size_t OUT_ELEMS = (size_t)B_ * S_ * D_;      // 4,194,304
    const size_t ATT_ELEMS = (size_t)B_ * H_ * S_ * S_; // 134,217,728

    float* scores_ptr = nullptr;
    cudaGetSymbolAddress((void**)&scores_ptr, g_scores);

    // weights destination: second chunk of d_out if present, else scratch
    float* wdst = ((size_t)out_size >= OUT_ELEMS + ATT_ELEMS) ? (out + OUT_ELEMS)
                                                              : scores_ptr;

    float *qp, *kp, *vp, *ap;
    cudaGetSymbolAddress((void**)&qp, g_q);
    cudaGetSymbolAddress((void**)&kp, g_kT);
    cudaGetSymbolAddress((void**)&vp, g_v);
    cudaGetSymbolAddress((void**)&ap, g_attn);

    // 1) QKV: [4096,1024] @ [1024,3072], scatter into q / kT / v
    {
        dim3 grid(3 * D_ / 128, (B_ * S_) / 128, 1);
        EpiQKV epi{b_qkv};
        tgemm_kernel<128, 128, 64, 32, EpiQKV><<<grid, 256>>>(
            query, W_qkv, D_, D_, 3 * D_, 0LL, 0LL, epi);
    }

    // 2) scores: per (b,h) [2048,64] @ [64,2048] -> wdst directly (scaled)
    {
        dim3 grid(S_ / 128, S_ / 128, B_ * H_);
        EpiScore epi{wdst};
        tgemm_kernel<128, 128, 64, 32, EpiScore><<<grid, 256>>>(
            qp, kp, HD_, HD_, S_,
            (long long)S_ * HD_, (long long)HD_ * S_, epi);
    }

    // 3) softmax rows, in place on wdst
    {
        softmax_kernel<<<B_ * H_ * S_, 256>>>(wdst);
    }

    // 4) AV: per (b,h) [2048,2048] @ [2048,64] -> g_attn (B,S,H,Hd layout)
    {
        dim3 grid(HD_ / 64, S_ / 128, B_ * H_);
        EpiAV epi{};
        tgemm_kernel<128, 64, 32, 32, EpiAV><<<grid, 256>>>(
            wdst, vp, S_, S_, HD_,
            (long long)S_ * S_, (long long)S_ * HD_, epi);
    }

    // 5) out proj: [4096,1024] @ [1024,1024] + b -> d_out head
    {
        dim3 grid(D_ / 128, (B_ * S_) / 128, 1);
        EpiOut epi{b_out, out};
        tgemm_kernel<128, 128, 64, 32, EpiOut><<<grid, 256>>>(
            ap, W_out, D_, D_, D_, 0LL, 0LL, epi);
    }
}

// round 5
// speedup vs baseline: 1.3324x; 1.3324x over previous
#include <cuda_runtime.h>
#include <cstdio>
#include <cstdint>

#define B_ 2
#define S_ 2048
#define D_ 1024
#define H_ 16
#define HD_ 64

// ---------------- scratch (device globals; no allocation allowed) ----------------
__device__ float g_q[(size_t)B_ * H_ * S_ * HD_];     // [B,H,S,Hd]
__device__ float g_kT[(size_t)B_ * H_ * HD_ * S_];    // [B,H,Hd,S]
__device__ float g_v[(size_t)B_ * H_ * S_ * HD_];     // [B,H,S,Hd]
__device__ float g_attn[(size_t)B_ * S_ * D_];        // [B,S,D] (H,Hd interleaved)
__device__ float g_scores[(size_t)B_ * H_ * S_ * S_]; // fallback weights buffer

// ---------------- helpers ----------------
__device__ __forceinline__ uint32_t f2tf32(float x) {
    uint32_t u;
    asm("cvt.rna.tf32.f32 %0, %1;" : "=r"(u) : "f"(x));
    return u;
}

__device__ __forceinline__ void mma_tf32(float& c0, float& c1, float& c2, float& c3,
                                         uint32_t a0, uint32_t a1, uint32_t a2, uint32_t a3,
                                         uint32_t b0, uint32_t b1) {
    asm volatile(
        "mma.sync.aligned.m16n8k8.row.col.f32.tf32.tf32.f32 "
        "{%0,%1,%2,%3}, {%4,%5,%6,%7}, {%8,%9}, {%0,%1,%2,%3};"
        : "+f"(c0), "+f"(c1), "+f"(c2), "+f"(c3)
        : "r"(a0), "r"(a1), "r"(a2), "r"(a3), "r"(b0), "r"(b1));
}

// ---------------- epilogues for projection GEMMs ----------------
struct EpiQKV {
    const float* bias;
    __device__ __forceinline__ void operator()(int, int m, int n, float v) const {
        v += bias[n];
        int part = n >> 10;           // 0=q 1=k 2=v
        int rem = n & 1023;
        int h = rem >> 6;
        int d = rem & 63;
        int b = m >> 11;
        int s = m & 2047;
        size_t bh = (size_t)(b * H_ + h);
        if (part == 0)
            g_q[(bh * S_ + s) * HD_ + d] = v;
        else if (part == 1)
            g_kT[(bh * HD_ + d) * S_ + s] = v;
        else
            g_v[(bh * S_ + s) * HD_ + d] = v;
    }
};

struct EpiOut {
    const float* bias;
    float* out;
    __device__ __forceinline__ void operator()(int, int m, int n, float v) const {
        out[(size_t)m * D_ + n] = v + bias[n];
    }
};

// ---------------- tensor-core tf32 GEMM (double-buffered via register prefetch) ----
template <int BM, int BN, int WM, int WN, class Epi>
__global__ void __launch_bounds__(256, 2)
tgemm_kernel(const float* __restrict__ Aall, const float* __restrict__ Ball,
             int K, int lda, int ldb,
             long long strideA, long long strideB, Epi epi) {
    constexpr int BK = 32;
    constexpr int NWM = BM / WM;
    constexpr int NWN = BN / WN;
    static_assert(NWM * NWN == 8, "8 warps");
    constexpr int MT = WM / 16;
    constexpr int NT = WN / 8;
    constexpr int A4 = BM * BK / 4 / 256;
    constexpr int B4 = BK * BN / 4 / 256;
    static_assert(A4 * 256 * 4 == BM * BK, "A tile");
    static_assert(B4 * 256 * 4 == BK * BN, "B tile");

    __shared__ uint32_t sA[BM * BK];
    __shared__ uint32_t sB[BK * BN];

    const int bz = blockIdx.z;
    const float* A = Aall + (size_t)bz * strideA;
    const float* Bp = Ball + (size_t)bz * strideB;

    const int tid = threadIdx.x;
    const int lane = tid & 31;
    const int warp = tid >> 5;
    const int wm = warp / NWN;
    const int wn = warp % NWN;
    const int row0 = blockIdx.y * BM;
    const int col0 = blockIdx.x * BN;

    float acc[MT][NT][4];
#pragma unroll
    for (int i = 0; i < MT; i++)
#pragma unroll
        for (int j = 0; j < NT; j++)
#pragma unroll
            for (int v = 0; v < 4; v++) acc[i][j][v] = 0.f;

    float4 pa[A4], pb[B4];
    // prologue load of tile 0
#pragma unroll
    for (int it = 0; it < A4; ++it) {
        int idx = tid + it * 256;
        int r = idx >> 3, c4 = (idx & 7) << 2;
        pa[it] = *reinterpret_cast<const float4*>(&A[(size_t)(row0 + r) * lda + c4]);
    }
#pragma unroll
    for (int it = 0; it < B4; ++it) {
        int idx = tid + it * 256;
        int r = idx / (BN / 4), c4 = (idx % (BN / 4)) << 2;
        pb[it] = *reinterpret_cast<const float4*>(&Bp[(size_t)r * ldb + col0 + c4]);
    }

    for (int k0 = 0; k0 < K; k0 += BK) {
        // ---- scatter prefetched tile into fragment-major smem ----
#pragma unroll
        for (int it = 0; it < A4; ++it) {
            int idx = tid + it * 256;
            int r = idx >> 3, c4 = (idx & 7) << 2;
            int mt = r >> 4, rw = r & 15;
            float vv[4] = {pa[it].x, pa[it].y, pa[it].z, pa[it].w};
#pragma unroll
            for (int j = 0; j < 4; j++) {
                int c = c4 + j;
                int ks = c >> 3, ci = c & 7;
                int ln = ((rw & 7) << 2) | (ci & 3);
                int slot = (rw >> 3) | ((ci >> 2) << 1);
                sA[((((mt << 2) + ks) << 5) + ln) * 4 + slot] = f2tf32(vv[j]);
            }
        }
#pragma unroll
        for (int it = 0; it < B4; ++it) {
            int idx = tid + it * 256;
            int r = idx / (BN / 4), c4 = (idx % (BN / 4)) << 2;
            int ks = r >> 3, rw = r & 7;
            float vv[4] = {pb[it].x, pb[it].y, pb[it].z, pb[it].w};
#pragma unroll
            for (int j = 0; j < 4; j++) {
                int n = c4 + j;
                int nt = n >> 3, ci = n & 7;
                int ln = (ci << 2) | (rw & 3);
                int slot = rw >> 2;
                sB[((((nt << 2) + ks) << 5) + ln) * 2 + slot] = f2tf32(vv[j]);
            }
        }
        __syncthreads();

        // ---- prefetch next tile (overlaps with MMAs below) ----
        if (k0 + BK < K) {
#pragma unroll
            for (int it = 0; it < A4; ++it) {
                int idx = tid + it * 256;
                int r = idx >> 3, c4 = (idx & 7) << 2;
                pa[it] = *reinterpret_cast<const float4*>(
                    &A[(size_t)(row0 + r) * lda + k0 + BK + c4]);
            }
#pragma unroll
            for (int it = 0; it < B4; ++it) {
                int idx = tid + it * 256;
                int r = idx / (BN / 4), c4 = (idx % (BN / 4)) << 2;
                pb[it] = *reinterpret_cast<const float4*>(
                    &Bp[(size_t)(k0 + BK + r) * ldb + col0 + c4]);
            }
        }

        // ---- compute ----
#pragma unroll
        for (int ks = 0; ks < 4; ks++) {
            uint4 af[MT];
            uint2 bf[NT];
#pragma unroll
            for (int i = 0; i < MT; i++) {
                int frag = (wm * MT + i) * 4 + ks;
                af[i] = *reinterpret_cast<const uint4*>(&sA[((frag << 5) + lane) * 4]);
            }
#pragma unroll
            for (int j = 0; j < NT; j++) {
                int frag = (wn * NT + j) * 4 + ks;
                bf[j] = *reinterpret_cast<const uint2*>(&sB[((frag << 5) + lane) * 2]);
            }
#pragma unroll
            for (int i = 0; i < MT; i++)
#pragma unroll
                for (int j = 0; j < NT; j++)
                    mma_tf32(acc[i][j][0], acc[i][j][1], acc[i][j][2], acc[i][j][3],
                             af[i].x, af[i].y, af[i].z, af[i].w, bf[j].x, bf[j].y);
        }
        __syncthreads();
    }

#pragma unroll
    for (int i = 0; i < MT; i++) {
        int m0 = row0 + wm * WM + i * 16 + (lane >> 2);
#pragma unroll
        for (int j = 0; j < NT; j++) {
            int n0 = col0 + wn * WN + j * 8 + ((lane & 3) << 1);
            epi(bz, m0, n0, acc[i][j][0]);
            epi(bz, m0, n0 + 1, acc[i][j][1]);
            epi(bz, m0 + 8, n0, acc[i][j][2]);
            epi(bz, m0 + 8, n0 + 1, acc[i][j][3]);
        }
    }
}

// ---------------- fused attention: scores + softmax + weights-write + AV -------
// Grid: (S_/128, B_*H_). CTA = 256 thr, 8 warps (4 along M, 2 along N).
// Pass 1: online row max / sum over all k-blocks (S recomputed, never stored).
// Pass 2: recompute S, w = exp(s-m)/l -> gmem weights + smem frags, O += w @ V.
// smem (uint32 units): sQ 8192 | sW 8192 | sK 4096 | sV 4096 | f32: sm 128,
//                      sl 128, sredm 256, sredl 256  => 101376 bytes
__global__ void __launch_bounds__(256, 2)
fused_attn_kernel(const float* __restrict__ qg, const float* __restrict__ kTg,
                  const float* __restrict__ vg, float* __restrict__ wout,
                  float* __restrict__ og) {
    extern __shared__ uint32_t smem[];
    uint32_t* sQ = smem;
    uint32_t* sW = smem + 8192;
    uint32_t* sK = smem + 16384;
    uint32_t* sV = smem + 20480;
    float* sm = (float*)(smem + 24576);
    float* sl = (float*)(smem + 24704);
    float* sredm = (float*)(smem + 24832);
    float* sredl = (float*)(smem + 25088);

    const int tid = threadIdx.x;
    const int lane = tid & 31;
    const int warp = tid >> 5;
    const int wm = warp >> 1;   // 0..3
    const int wn = warp & 1;    // 0..1
    const int g = lane >> 2;
    const int qd = lane & 3;
    const int row0 = blockIdx.x * 128;
    const int bh = blockIdx.y;

    const float* Q = qg + (size_t)bh * S_ * HD_;
    const float* KT = kTg + (size_t)bh * HD_ * S_;
    const float* V = vg + (size_t)bh * S_ * HD_;

    // ---- stage Q once (scaled by 1/sqrt(Hd) = 0.125) ----
#pragma unroll
    for (int it = 0; it < 8; it++) {
        int idx = tid + it * 256;
        int r = idx >> 4, c4 = (idx & 15) << 2;
        float4 val = *reinterpret_cast<const float4*>(&Q[(size_t)(row0 + r) * HD_ + c4]);
        int mt = r >> 4, rw = r & 15;
        float vv[4] = {val.x, val.y, val.z, val.w};
#pragma unroll
        for (int j = 0; j < 4; j++) {
            int c = c4 + j, ks = c >> 3, ci = c & 7;
            int ln = ((rw & 7) << 2) | (ci & 3);
            int slot = (rw >> 3) | ((ci >> 2) << 1);
            sQ[((((mt << 3) + ks) << 5) + ln) * 4 + slot] = f2tf32(vv[j] * 0.125f);
        }
    }
    if (tid < 128) { sm[tid] = -1e30f; sl[tid] = 0.f; }
    __syncthreads();

    // ================= PASS 1: row max / sum =================
    for (int kb = 0; kb < S_ / 64; kb++) {
        const int col0k = kb * 64;
        // stage K block: B[k=d][n=seq]
#pragma unroll
        for (int it = 0; it < 4; it++) {
            int idx = tid + it * 256;
            int r = idx >> 4, c4 = (idx & 15) << 2;
            float4 val = *reinterpret_cast<const float4*>(&KT[(size_t)r * S_ + col0k + c4]);
            int ks = r >> 3, rw = r & 7;
            float vv[4] = {val.x, val.y, val.z, val.w};
#pragma unroll
            for (int j = 0; j < 4; j++) {
                int n = c4 + j, nt = n >> 3, ci = n & 7;
                int ln = (ci << 2) | (rw & 3);
                int slot = rw >> 2;
                sK[((((nt << 3) + ks) << 5) + ln) * 2 + slot] = f2tf32(vv[j]);
            }
        }
        __syncthreads();

        // S = Qs @ K^T  (128x64)
        float sacc[2][4][4];
#pragma unroll
        for (int i = 0; i < 2; i++)
#pragma unroll
            for (int j = 0; j < 4; j++)
#pragma unroll
                for (int v = 0; v < 4; v++) sacc[i][j][v] = 0.f;
#pragma unroll
        for (int ks = 0; ks < 8; ks++) {
            uint4 af[2];
            uint2 bf[4];
#pragma unroll
            for (int i = 0; i < 2; i++)
                af[i] = *reinterpret_cast<const uint4*>(
                    &sQ[((((wm * 2 + i) * 8 + ks) << 5) + lane) * 4]);
#pragma unroll
            for (int j = 0; j < 4; j++)
                bf[j] = *reinterpret_cast<const uint2*>(
                    &sK[((((wn * 4 + j) * 8 + ks) << 5) + lane) * 2]);
#pragma unroll
            for (int i = 0; i < 2; i++)
#pragma unroll
                for (int j = 0; j < 4; j++)
                    mma_tf32(sacc[i][j][0], sacc[i][j][1], sacc[i][j][2], sacc[i][j][3],
                             af[i].x, af[i].y, af[i].z, af[i].w, bf[j].x, bf[j].y);
        }

        // partial row max per warp-half
#pragma unroll
        for (int i = 0; i < 2; i++) {
            int r0 = wm * 32 + i * 16 + g;
            float mx0 = -1e30f, mx1 = -1e30f;
#pragma unroll
            for (int j = 0; j < 4; j++) {
                mx0 = fmaxf(mx0, fmaxf(sacc[i][j][0], sacc[i][j][1]));
                mx1 = fmaxf(mx1, fmaxf(sacc[i][j][2], sacc[i][j][3]));
            }
            mx0 = fmaxf(mx0, __shfl_xor_sync(0xffffffffu, mx0, 1));
            mx0 = fmaxf(mx0, __shfl_xor_sync(0xffffffffu, mx0, 2));
            mx1 = fmaxf(mx1, __shfl_xor_sync(0xffffffffu, mx1, 1));
            mx1 = fmaxf(mx1, __shfl_xor_sync(0xffffffffu, mx1, 2));
            if (qd == 0) {
                sredm[wn * 128 + r0] = mx0;
                sredm[wn * 128 + r0 + 8] = mx1;
            }
        }
        __syncthreads();

        // exp-sum against m_new
#pragma unroll
        for (int i = 0; i < 2; i++) {
            int r0 = wm * 32 + i * 16 + g;
            float mn0 = fmaxf(sm[r0], fmaxf(sredm[r0], sredm[128 + r0]));
            float mn1 = fmaxf(sm[r0 + 8], fmaxf(sredm[r0 + 8], sredm[128 + r0 + 8]));
            float s0 = 0.f, s1 = 0.f;
#pragma unroll
            for (int j = 0; j < 4; j++) {
                s0 += __expf(sacc[i][j][0] - mn0) + __expf(sacc[i][j][1] - mn0);
                s1 += __expf(sacc[i][j][2] - mn1) + __expf(sacc[i][j][3] - mn1);
            }
            s0 += __shfl_xor_sync(0xffffffffu, s0, 1);
            s0 += __shfl_xor_sync(0xffffffffu, s0, 2);
            s1 += __shfl_xor_sync(0xffffffffu, s1, 1);
            s1 += __shfl_xor_sync(0xffffffffu, s1, 2);
            if (qd == 0) {
                sredl[wn * 128 + r0] = s0;
                sredl[wn * 128 + r0 + 8] = s1;
            }
        }
        __syncthreads();

        if (tid < 128) {
            float mn = fmaxf(sm[tid], fmaxf(sredm[tid], sredm[128 + tid]));
            sl[tid] = sl[tid] * __expf(sm[tid] - mn) + sredl[tid] + sredl[128 + tid];
            sm[tid] = mn;
        }
        __syncthreads();
    }

    if (tid < 128) sl[tid] = 1.0f / sl[tid];
    __syncthreads();

    // ================= PASS 2: weights out + O accumulate =================
    float acc_o[2][4][4];
#pragma unroll
    for (int i = 0; i < 2; i++)
#pragma unroll
        for (int j = 0; j < 4; j++)
#pragma unroll
            for (int v = 0; v < 4; v++) acc_o[i][j][v] = 0.f;

    for (int kb = 0; kb < S_ / 64; kb++) {
        const int col0k = kb * 64;
        // stage K block
#pragma unroll
        for (int it = 0; it < 4; it++) {
            int idx = tid + it * 256;
            int r = idx >> 4, c4 = (idx & 15) << 2;
            float4 val = *reinterpret_cast<const float4*>(&KT[(size_t)r * S_ + col0k + c4]);
            int ks = r >> 3, rw = r & 7;
            float vv[4] = {val.x, val.y, val.z, val.w};
#pragma unroll
            for (int j = 0; j < 4; j++) {
                int n = c4 + j, nt = n >> 3, ci = n & 7;
                int ln = (ci << 2) | (rw & 3);
                int slot = rw >> 2;
                sK[((((nt << 3) + ks) << 5) + ln) * 2 + slot] = f2tf32(vv[j]);
            }
        }
        // stage V block: B[k=seq][n=d]
#pragma unroll
        for (int it = 0; it < 4; it++) {
            int idx = tid + it * 256;
            int r = idx >> 4, c4 = (idx & 15) << 2;
            float4 val = *reinterpret_cast<const float4*>(
                &V[(size_t)(col0k + r) * HD_ + c4]);
            int ks = r >> 3, rw = r & 7;
            float vv[4] = {val.x, val.y, val.z, val.w};
#pragma unroll
            for (int j = 0; j < 4; j++) {
                int n = c4 + j, nt = n >> 3, ci = n & 7;
                int ln = (ci << 2) | (rw & 3);
                int slot = rw >> 2;
                sV[((((nt << 3) + ks) << 5) + ln) * 2 + slot] = f2tf32(vv[j]);
            }
        }
        __syncthreads();

        // recompute S
        float sacc[2][4][4];
#pragma unroll
        for (int i = 0; i < 2; i++)
#pragma unroll
            for (int j = 0; j < 4; j++)
#pragma unroll
                for (int v = 0; v < 4; v++) sacc[i][j][v] = 0.f;
#pragma unroll
        for (int ks = 0; ks < 8; ks++) {
            uint4 af[2];
            uint2 bf[4];
#pragma unroll
            for (int i = 0; i < 2; i++)
                af[i] = *reinterpret_cast<const uint4*>(
                    &sQ[((((wm * 2 + i) * 8 + ks) << 5) + lane) * 4]);
#pragma unroll
            for (int j = 0; j < 4; j++)
                bf[j] = *reinterpret_cast<const uint2*>(
                    &sK[((((wn * 4 + j) * 8 + ks) << 5) + lane) * 2]);
#pragma unroll
            for (int i = 0; i < 2; i++)
#pragma unroll
                for (int j = 0; j < 4; j++)
                    mma_tf32(sacc[i][j][0], sacc[i][j][1], sacc[i][j][2], sacc[i][j][3],
                             af[i].x, af[i].y, af[i].z, af[i].w, bf[j].x, bf[j].y);
        }

        // w = exp(s - m) / l : write gmem + scatter to sW frags
#pragma unroll
        for (int i = 0; i < 2; i++) {
            int r0 = wm * 32 + i * 16 + g;
            float mn0 = sm[r0], il0 = sl[r0];
            float mn1 = sm[r0 + 8], il1 = sl[r0 + 8];
#pragma unroll
            for (int j = 0; j < 4; j++) {
                int c0 = wn * 32 + j * 8 + qd * 2;
                float w00 = __expf(sacc[i][j][0] - mn0) * il0;
                float w01 = __expf(sacc[i][j][1] - mn0) * il0;
                float w10 = __expf(sacc[i][j][2] - mn1) * il1;
                float w11 = __expf(sacc[i][j][3] - mn1) * il1;
                size_t base = ((size_t)bh * S_ + row0 + r0) * S_ + col0k + c0;
                float2 p0 = {w00, w01};
                float2 p1 = {w10, w11};
                *reinterpret_cast<float2*>(&wout[base]) = p0;
                *reinterpret_cast<float2*>(&wout[base + (size_t)8 * S_]) = p1;
                // scatter into A-fragment layout (M=128, K=64 over seq)
                {
                    int rr = r0, rw2 = rr & 15, mt = rr >> 4;
                    int c = c0, ks = c >> 3, ci = c & 7;
                    int ln = ((rw2 & 7) << 2) | (ci & 3);
                    int slot = (rw2 >> 3) | ((ci >> 2) << 1);
                    sW[((((mt << 3) + ks) << 5) + ln) * 4 + slot] = f2tf32(w00);
                    ci = (c + 1) & 7;
                    ln = ((rw2 & 7) << 2) | (ci & 3);
                    slot = (rw2 >> 3) | ((ci >> 2) << 1);
                    sW[((((mt << 3) + ks) << 5) + ln) * 4 + slot] = f2tf32(w01);
                    rr = r0 + 8;
                    rw2 = rr & 15;
                    mt = rr >> 4;
                    ci = c & 7;
                    ln = ((rw2 & 7) << 2) | (ci & 3);
                    slot = (rw2 >> 3) | ((ci >> 2) << 1);
                    sW[((((mt << 3) + ks) << 5) + ln) * 4 + slot] = f2tf32(w10);
                    ci = (c + 1) & 7;
                    ln = ((rw2 & 7) << 2) | (ci & 3);
                    slot = (rw2 >> 3) | ((ci >> 2) << 1);
                    sW[((((mt << 3) + ks) << 5) + ln) * 4 + slot] = f2tf32(w11);
                }
            }
        }
        __syncthreads();

        // O += w @ V
#pragma unroll
        for (int ks = 0; ks < 8; ks++) {
            uint4 af[2];
            uint2 bf[4];
#pragma unroll
            for (int i = 0; i < 2; i++)
                af[i] = *reinterpret_cast<const uint4*>(
                    &sW[((((wm * 2 + i) * 8 + ks) << 5) + lane) * 4]);
#pragma unroll
            for (int j = 0; j < 4; j++)
                bf[j] = *reinterpret_cast<const uint2*>(
                    &sV[((((wn * 4 + j) * 8 + ks) << 5) + lane) * 2]);
#pragma unroll
            for (int i = 0; i < 2; i++)
#pragma unroll
                for (int j = 0; j < 4; j++)
                    mma_tf32(acc_o[i][j][0], acc_o[i][j][1], acc_o[i][j][2], acc_o[i][j][3],
                             af[i].x, af[i].y, af[i].z, af[i].w, bf[j].x, bf[j].y);
        }
        __syncthreads();
    }

    // epilogue: O -> g_attn [b][s][h][hd]
    const int b = bh >> 4;
    const int h = bh & 15;
#pragma unroll
    for (int i = 0; i < 2; i++) {
        int gr = row0 + wm * 32 + i * 16 + g;
#pragma unroll
        for (int j = 0; j < 4; j++) {
            int c0 = wn * 32 + j * 8 + qd * 2;
            float2 p0 = {acc_o[i][j][0], acc_o[i][j][1]};
            float2 p1 = {acc_o[i][j][2], acc_o[i][j][3]};
            size_t a0 = (((size_t)b * S_ + gr) * H_ + h) * HD_ + c0;
            size_t a1 = (((size_t)b * S_ + gr + 8) * H_ + h) * HD_ + c0;
            *reinterpret_cast<float2*>(&og[a0]) = p0;
            *reinterpret_cast<float2*>(&og[a1]) = p1;
        }
    }
}

// ---------------- launch ----------------
extern "C" void kernel_launch(void* const* d_in, const int* in_sizes, int n_in,
                              void* d_out, int out_size) {
    const float* query = (const float*)d_in[0]; // [B,S,D]
    const float* W_qkv = (const float*)d_in[1]; // [D,3D]
    const float* b_qkv = (const float*)d_in[2]; // [3D]
    const float* W_out = (const float*)d_in[3]; // [D,D]
    const float* b_out = (const float*)d_in[4]; // [D]
    float* out = (float*)d_out;

    const size_t OUT_ELEMS = (size_t)B_ * S_ * D_;      // 4,194,304
    const size_t ATT_ELEMS = (size_t)B_ * H_ * S_ * S_; // 134,217,728

    float* scores_ptr = nullptr;
    cudaGetSymbolAddress((void**)&scores_ptr, g_scores);

    float* wdst = ((size_t)out_size >= OUT_ELEMS + ATT_ELEMS) ? (out + OUT_ELEMS)
                                                              : scores_ptr;

    float *qp, *kp, *vp, *ap;
    cudaGetSymbolAddress((void**)&qp, g_q);
    cudaGetSymbolAddress((void**)&kp, g_kT);
    cudaGetSymbolAddress((void**)&vp, g_v);
    cudaGetSymbolAddress((void**)&ap, g_attn);

    static bool smem_set = false;
    if (!smem_set) {
        cudaFuncSetAttribute(fused_attn_kernel,
                             cudaFuncAttributeMaxDynamicSharedMemorySize, 101376);
        smem_set = true;
    }

    // 1) QKV projection: [4096,1024] @ [1024,3072] -> q / kT / v
    {
        dim3 grid(3 * D_ / 128, (B_ * S_) / 128, 1);
        EpiQKV epi{b_qkv};
        tgemm_kernel<128, 128, 64, 32, EpiQKV><<<grid, 256>>>(
            query, W_qkv, D_, D_, 3 * D_, 0LL, 0LL, epi);
    }

    // 2) fused attention: scores + softmax (+weights out) + AV
    {
        dim3 grid(S_ / 128, B_ * H_);
        fused_attn_kernel<<<grid, 256, 101376>>>(qp, kp, vp, wdst, ap);
    }

    // 3) out proj: [4096,1024] @ [1024,1024] + b -> d_out head
    {
        dim3 grid(D_ / 128, (B_ * S_) / 128, 1);
        EpiOut epi{b_out, out};
        tgemm_kernel<128, 128, 64, 32, EpiOut><<<grid, 256>>>(
            ap, W_out, D_, D_, D_, 0LL, 0LL, epi);
    }
}

// round 6
// speedup vs baseline: 2.1896x; 1.6433x over previous
#include <cuda_runtime.h>
#include <cstdio>
#include <cstdint>

#define B_ 2
#define S_ 2048
#define D_ 1024
#define H_ 16
#define HD_ 64
#define NKB_ 32   // S_/64 key blocks

// ---------------- scratch (device globals; no allocation allowed) ----------------
__device__ float g_q[(size_t)B_ * H_ * S_ * HD_];     // [B,H,S,Hd]
__device__ float g_kT[(size_t)B_ * H_ * HD_ * S_];    // [B,H,Hd,S]
__device__ float g_v[(size_t)B_ * H_ * S_ * HD_];     // [B,H,S,Hd]
__device__ float g_attn[(size_t)B_ * S_ * D_];        // [B,S,D]
__device__ float g_scores[(size_t)B_ * H_ * S_ * S_]; // fallback weights buffer
__device__ float g_mkb[(size_t)B_ * H_ * S_ * NKB_];  // running max at each kb
__device__ float g_mfin[(size_t)B_ * H_ * S_];        // final max per row
__device__ float g_linv[(size_t)B_ * H_ * S_];        // 1/l per row

// ---------------- helpers ----------------
__device__ __forceinline__ uint32_t f2tf32(float x) {
    uint32_t u;
    asm("cvt.rna.tf32.f32 %0, %1;" : "=r"(u) : "f"(x));
    return u;
}

__device__ __forceinline__ void mma_tf32(float& c0, float& c1, float& c2, float& c3,
                                         uint32_t a0, uint32_t a1, uint32_t a2, uint32_t a3,
                                         uint32_t b0, uint32_t b1) {
    asm volatile(
        "mma.sync.aligned.m16n8k8.row.col.f32.tf32.tf32.f32 "
        "{%0,%1,%2,%3}, {%4,%5,%6,%7}, {%8,%9}, {%0,%1,%2,%3};"
        : "+f"(c0), "+f"(c1), "+f"(c2), "+f"(c3)
        : "r"(a0), "r"(a1), "r"(a2), "r"(a3), "r"(b0), "r"(b1));
}

// padded fragment-layout strides (words) to kill staging bank conflicts
#define ASTRIDE 132   // A-frag: 32 lanes x 4 slots = 128 + 4 pad
#define BSTRIDE 66    // B-frag: 32 lanes x 2 slots = 64 + 2 pad

// ---------------- epilogues for projection GEMMs ----------------
struct EpiQKV {
    const float* bias;
    __device__ __forceinline__ void operator()(int, int m, int n, float v) const {
        v += bias[n];
        int part = n >> 10;
        int rem = n & 1023;
        int h = rem >> 6;
        int d = rem & 63;
        int b = m >> 11;
        int s = m & 2047;
        size_t bh = (size_t)(b * H_ + h);
        if (part == 0)
            g_q[(bh * S_ + s) * HD_ + d] = v;
        else if (part == 1)
            g_kT[(bh * HD_ + d) * S_ + s] = v;
        else
            g_v[(bh * S_ + s) * HD_ + d] = v;
    }
};

struct EpiOut {
    const float* bias;
    float* out;
    __device__ __forceinline__ void operator()(int, int m, int n, float v) const {
        out[(size_t)m * D_ + n] = v + bias[n];
    }
};

// ---------------- tensor-core tf32 GEMM (register prefetch, padded smem) --------
template <int BM, int BN, int WM, int WN, class Epi>
__global__ void __launch_bounds__(256, 2)
tgemm_kernel(const float* __restrict__ Aall, const float* __restrict__ Ball,
             int K, int lda, int ldb,
             long long strideA, long long strideB, Epi epi) {
    constexpr int BK = 32;
    constexpr int NWM = BM / WM;
    constexpr int NWN = BN / WN;
    static_assert(NWM * NWN == 8, "8 warps");
    constexpr int MT = WM / 16;
    constexpr int NT = WN / 8;
    constexpr int A4 = BM * BK / 4 / 256;
    constexpr int B4 = BK * BN / 4 / 256;

    __shared__ uint32_t sA[(BM / 16) * 4 * ASTRIDE];
    __shared__ uint32_t sB[(BN / 8) * 4 * BSTRIDE];

    const int bz = blockIdx.z;
    const float* A = Aall + (size_t)bz * strideA;
    const float* Bp = Ball + (size_t)bz * strideB;

    const int tid = threadIdx.x;
    const int lane = tid & 31;
    const int warp = tid >> 5;
    const int wm = warp / NWN;
    const int wn = warp % NWN;
    const int row0 = blockIdx.y * BM;
    const int col0 = blockIdx.x * BN;

    float acc[MT][NT][4];
#pragma unroll
    for (int i = 0; i < MT; i++)
#pragma unroll
        for (int j = 0; j < NT; j++)
#pragma unroll
            for (int v = 0; v < 4; v++) acc[i][j][v] = 0.f;

    float4 pa[A4], pb[B4];
#pragma unroll
    for (int it = 0; it < A4; ++it) {
        int idx = tid + it * 256;
        int r = idx >> 3, c4 = (idx & 7) << 2;
        pa[it] = *reinterpret_cast<const float4*>(&A[(size_t)(row0 + r) * lda + c4]);
    }
#pragma unroll
    for (int it = 0; it < B4; ++it) {
        int idx = tid + it * 256;
        int r = idx / (BN / 4), c4 = (idx % (BN / 4)) << 2;
        pb[it] = *reinterpret_cast<const float4*>(&Bp[(size_t)r * ldb + col0 + c4]);
    }

    for (int k0 = 0; k0 < K; k0 += BK) {
#pragma unroll
        for (int it = 0; it < A4; ++it) {
            int idx = tid + it * 256;
            int r = idx >> 3, c4 = (idx & 7) << 2;
            int mt = r >> 4, rw = r & 15;
            float vv[4] = {pa[it].x, pa[it].y, pa[it].z, pa[it].w};
#pragma unroll
            for (int j = 0; j < 4; j++) {
                int c = c4 + j;
                int ks = c >> 3, ci = c & 7;
                int ln = ((rw & 7) << 2) | (ci & 3);
                int slot = (rw >> 3) | ((ci >> 2) << 1);
                sA[((mt << 2) + ks) * ASTRIDE + ln * 4 + slot] = f2tf32(vv[j]);
            }
        }
#pragma unroll
        for (int it = 0; it < B4; ++it) {
            int idx = tid + it * 256;
            int r = idx / (BN / 4), c4 = (idx % (BN / 4)) << 2;
            int ks = r >> 3, rw = r & 7;
            float vv[4] = {pb[it].x, pb[it].y, pb[it].z, pb[it].w};
#pragma unroll
            for (int j = 0; j < 4; j++) {
                int n = c4 + j;
                int nt = n >> 3, ci = n & 7;
                int ln = (ci << 2) | (rw & 3);
                int slot = rw >> 2;
                sB[((nt << 2) + ks) * BSTRIDE + ln * 2 + slot] = f2tf32(vv[j]);
            }
        }
        __syncthreads();

        if (k0 + BK < K) {
#pragma unroll
            for (int it = 0; it < A4; ++it) {
                int idx = tid + it * 256;
                int r = idx >> 3, c4 = (idx & 7) << 2;
                pa[it] = *reinterpret_cast<const float4*>(
                    &A[(size_t)(row0 + r) * lda + k0 + BK + c4]);
            }
#pragma unroll
            for (int it = 0; it < B4; ++it) {
                int idx = tid + it * 256;
                int r = idx / (BN / 4), c4 = (idx % (BN / 4)) << 2;
                pb[it] = *reinterpret_cast<const float4*>(
                    &Bp[(size_t)(k0 + BK + r) * ldb + col0 + c4]);
            }
        }

#pragma unroll
        for (int ks = 0; ks < 4; ks++) {
            uint4 af[MT];
            uint2 bf[NT];
#pragma unroll
            for (int i = 0; i < MT; i++)
                af[i] = *reinterpret_cast<const uint4*>(
                    &sA[((wm * MT + i) * 4 + ks) * ASTRIDE + lane * 4]);
#pragma unroll
            for (int j = 0; j < NT; j++)
                bf[j] = *reinterpret_cast<const uint2*>(
                    &sB[((wn * NT + j) * 4 + ks) * BSTRIDE + lane * 2]);
#pragma unroll
            for (int i = 0; i < MT; i++)
#pragma unroll
                for (int j = 0; j < NT; j++)
                    mma_tf32(acc[i][j][0], acc[i][j][1], acc[i][j][2], acc[i][j][3],
                             af[i].x, af[i].y, af[i].z, af[i].w, bf[j].x, bf[j].y);
        }
        __syncthreads();
    }

#pragma unroll
    for (int i = 0; i < MT; i++) {
        int m0 = row0 + wm * WM + i * 16 + (lane >> 2);
#pragma unroll
        for (int j = 0; j < NT; j++) {
            int n0 = col0 + wn * WN + j * 8 + ((lane & 3) << 1);
            epi(bz, m0, n0, acc[i][j][0]);
            epi(bz, m0, n0 + 1, acc[i][j][1]);
            epi(bz, m0 + 8, n0, acc[i][j][2]);
            epi(bz, m0 + 8, n0 + 1, acc[i][j][3]);
        }
    }
}

// ---------------- single-pass flash attention ----------------
// Grid (S_/128, B_*H_), 256 thr, 8 warps = 4(wm) x 2(wn). 64-col key blocks.
// Writes UNNORMALIZED p = exp(s - m_kb) to wout; records m_kb, m_fin, 1/l for
// the rescale kernel. O accumulated online with rescaling; normalized on store.
// smem words: sQ 8448 | sW 8448 | sK 4224 | sV 4224 | sm 128 | sl 128 |
//             salpha 128 | sredm 256 | sredl 256 = 26240 words = 104960 B
#define SMEM_ATTN_BYTES 104960
__global__ void __launch_bounds__(256, 2)
fused_attn_kernel(const float* __restrict__ qg, const float* __restrict__ kTg,
                  const float* __restrict__ vg, float* __restrict__ wout,
                  float* __restrict__ og) {
    extern __shared__ uint32_t smem[];
    uint32_t* sQ = smem;
    uint32_t* sW = smem + 8448;
    uint32_t* sK = smem + 16896;
    uint32_t* sV = smem + 21120;
    float* sm = (float*)(smem + 25344);
    float* sl = (float*)(smem + 25472);
    float* salpha = (float*)(smem + 25600);
    float* sredm = (float*)(smem + 25728);
    float* sredl = (float*)(smem + 25984);

    const int tid = threadIdx.x;
    const int lane = tid & 31;
    const int warp = tid >> 5;
    const int wm = warp >> 1;
    const int wn = warp & 1;
    const int g = lane >> 2;
    const int qd = lane & 3;
    const int row0 = blockIdx.x * 128;
    const int bh = blockIdx.y;

    const float* Q = qg + (size_t)bh * S_ * HD_;
    const float* KT = kTg + (size_t)bh * HD_ * S_;
    const float* V = vg + (size_t)bh * S_ * HD_;

    // stage Q once (pre-scaled by 1/8)
#pragma unroll
    for (int it = 0; it < 8; it++) {
        int idx = tid + it * 256;
        int r = idx >> 4, c4 = (idx & 15) << 2;
        float4 val = *reinterpret_cast<const float4*>(&Q[(size_t)(row0 + r) * HD_ + c4]);
        int mt = r >> 4, rw = r & 15;
        float vv[4] = {val.x, val.y, val.z, val.w};
#pragma unroll
        for (int j = 0; j < 4; j++) {
            int c = c4 + j, ks = c >> 3, ci = c & 7;
            int ln = ((rw & 7) << 2) | (ci & 3);
            int slot = (rw >> 3) | ((ci >> 2) << 1);
            sQ[((mt << 3) + ks) * ASTRIDE + ln * 4 + slot] = f2tf32(vv[j] * 0.125f);
        }
    }
    if (tid < 128) { sm[tid] = -1e30f; sl[tid] = 0.f; }

    float acc_o[2][4][4];
#pragma unroll
    for (int i = 0; i < 2; i++)
#pragma unroll
        for (int j = 0; j < 4; j++)
#pragma unroll
            for (int v = 0; v < 4; v++) acc_o[i][j][v] = 0.f;
    __syncthreads();

    for (int kb = 0; kb < NKB_; kb++) {
        const int col0k = kb * 64;
        // stage K block (B-layout over n=seq, k=d)
#pragma unroll
        for (int it = 0; it < 4; it++) {
            int idx = tid + it * 256;
            int r = idx >> 4, c4 = (idx & 15) << 2;
            float4 val = *reinterpret_cast<const float4*>(&KT[(size_t)r * S_ + col0k + c4]);
            int ks = r >> 3, rw = r & 7;
            float vv[4] = {val.x, val.y, val.z, val.w};
#pragma unroll
            for (int j = 0; j < 4; j++) {
                int n = c4 + j, nt = n >> 3, ci = n & 7;
                int ln = (ci << 2) | (rw & 3);
                int slot = rw >> 2;
                sK[((nt << 3) + ks) * BSTRIDE + ln * 2 + slot] = f2tf32(vv[j]);
            }
        }
        // stage V block (B-layout over n=d, k=seq)
#pragma unroll
        for (int it = 0; it < 4; it++) {
            int idx = tid + it * 256;
            int r = idx >> 4, c4 = (idx & 15) << 2;
            float4 val = *reinterpret_cast<const float4*>(&V[(size_t)(col0k + r) * HD_ + c4]);
            int ks = r >> 3, rw = r & 7;
            float vv[4] = {val.x, val.y, val.z, val.w};
#pragma unroll
            for (int j = 0; j < 4; j++) {
                int n = c4 + j, nt = n >> 3, ci = n & 7;
                int ln = (ci << 2) | (rw & 3);
                int slot = rw >> 2;
                sV[((nt << 3) + ks) * BSTRIDE + ln * 2 + slot] = f2tf32(vv[j]);
            }
        }
        __syncthreads();

        // S = Q @ K^T (128x64)
        float sacc[2][4][4];
#pragma unroll
        for (int i = 0; i < 2; i++)
#pragma unroll
            for (int j = 0; j < 4; j++)
#pragma unroll
                for (int v = 0; v < 4; v++) sacc[i][j][v] = 0.f;
#pragma unroll
        for (int ks = 0; ks < 8; ks++) {
            uint4 af[2];
            uint2 bf[4];
#pragma unroll
            for (int i = 0; i < 2; i++)
                af[i] = *reinterpret_cast<const uint4*>(
                    &sQ[((wm * 2 + i) * 8 + ks) * ASTRIDE + lane * 4]);
#pragma unroll
            for (int j = 0; j < 4; j++)
                bf[j] = *reinterpret_cast<const uint2*>(
                    &sK[((wn * 4 + j) * 8 + ks) * BSTRIDE + lane * 2]);
#pragma unroll
            for (int i = 0; i < 2; i++)
#pragma unroll
                for (int j = 0; j < 4; j++)
                    mma_tf32(sacc[i][j][0], sacc[i][j][1], sacc[i][j][2], sacc[i][j][3],
                             af[i].x, af[i].y, af[i].z, af[i].w, bf[j].x, bf[j].y);
        }

        // block row-max
#pragma unroll
        for (int i = 0; i < 2; i++) {
            int r0 = wm * 32 + i * 16 + g;
            float mx0 = -1e30f, mx1 = -1e30f;
#pragma unroll
            for (int j = 0; j < 4; j++) {
                mx0 = fmaxf(mx0, fmaxf(sacc[i][j][0], sacc[i][j][1]));
                mx1 = fmaxf(mx1, fmaxf(sacc[i][j][2], sacc[i][j][3]));
            }
            mx0 = fmaxf(mx0, __shfl_xor_sync(0xffffffffu, mx0, 1));
            mx0 = fmaxf(mx0, __shfl_xor_sync(0xffffffffu, mx0, 2));
            mx1 = fmaxf(mx1, __shfl_xor_sync(0xffffffffu, mx1, 1));
            mx1 = fmaxf(mx1, __shfl_xor_sync(0xffffffffu, mx1, 2));
            if (qd == 0) {
                sredm[wn * 128 + r0] = mx0;
                sredm[wn * 128 + r0 + 8] = mx1;
            }
        }
        __syncthreads();

        // per-row m update + alpha + record m_kb
        if (tid < 128) {
            float mo = sm[tid];
            float mn = fmaxf(mo, fmaxf(sredm[tid], sredm[128 + tid]));
            salpha[tid] = __expf(mo - mn);
            sm[tid] = mn;
            g_mkb[((size_t)bh * S_ + row0 + tid) * NKB_ + kb] = mn;
        }
        __syncthreads();

        // p = exp(s - m_new): gmem write (unnormalized) + scatter + O rescale
#pragma unroll
        for (int i = 0; i < 2; i++) {
            int r0 = wm * 32 + i * 16 + g;
            float mn0 = sm[r0], mn1 = sm[r0 + 8];
            float a0 = salpha[r0], a1 = salpha[r0 + 8];
            float s0 = 0.f, s1 = 0.f;
#pragma unroll
            for (int j = 0; j < 4; j++) {
                int c0 = wn * 32 + j * 8 + qd * 2;
                float p00 = __expf(sacc[i][j][0] - mn0);
                float p01 = __expf(sacc[i][j][1] - mn0);
                float p10 = __expf(sacc[i][j][2] - mn1);
                float p11 = __expf(sacc[i][j][3] - mn1);
                s0 += p00 + p01;
                s1 += p10 + p11;
                size_t base = ((size_t)bh * S_ + row0 + r0) * S_ + col0k + c0;
                float2 q0 = {p00, p01};
                float2 q1 = {p10, p11};
                *reinterpret_cast<float2*>(&wout[base]) = q0;
                *reinterpret_cast<float2*>(&wout[base + (size_t)8 * S_]) = q1;
                // scatter into A-frag layout for the AV MMA
                {
                    int rr = r0, rw2 = rr & 15, mt = rr >> 4;
                    int c = c0, ks = c >> 3, ci = c & 7;
                    int ln = ((rw2 & 7) << 2) | (ci & 3);
                    int slot = (rw2 >> 3) | ((ci >> 2) << 1);
                    sW[((mt << 3) + ks) * ASTRIDE + ln * 4 + slot] = f2tf32(p00);
                    ci = (c + 1) & 7;
                    ln = ((rw2 & 7) << 2) | (ci & 3);
                    slot = (rw2 >> 3) | ((ci >> 2) << 1);
                    sW[((mt << 3) + ks) * ASTRIDE + ln * 4 + slot] = f2tf32(p01);
                    rr = r0 + 8; rw2 = rr & 15; mt = rr >> 4;
                    ci = c & 7;
                    ln = ((rw2 & 7) << 2) | (ci & 3);
                    slot = (rw2 >> 3) | ((ci >> 2) << 1);
                    sW[((mt << 3) + ks) * ASTRIDE + ln * 4 + slot] = f2tf32(p10);
                    ci = (c + 1) & 7;
                    ln = ((rw2 & 7) << 2) | (ci & 3);
                    slot = (rw2 >> 3) | ((ci >> 2) << 1);
                    sW[((mt << 3) + ks) * ASTRIDE + ln * 4 + slot] = f2tf32(p11);
                }
                // rescale O accumulators
                acc_o[i][j][0] *= a0; acc_o[i][j][1] *= a0;
                acc_o[i][j][2] *= a1; acc_o[i][j][3] *= a1;
            }
            s0 += __shfl_xor_sync(0xffffffffu, s0, 1);
            s0 += __shfl_xor_sync(0xffffffffu, s0, 2);
            s1 += __shfl_xor_sync(0xffffffffu, s1, 1);
            s1 += __shfl_xor_sync(0xffffffffu, s1, 2);
            if (qd == 0) {
                sredl[wn * 128 + r0] = s0;
                sredl[wn * 128 + r0 + 8] = s1;
            }
        }
        __syncthreads();

        // l update (reads salpha/sredl of this kb)
        if (tid < 128)
            sl[tid] = sl[tid] * salpha[tid] + sredl[tid] + sredl[128 + tid];

        // O += p @ V
#pragma unroll
        for (int ks = 0; ks < 8; ks++) {
            uint4 af[2];
            uint2 bf[4];
#pragma unroll
            for (int i = 0; i < 2; i++)
                af[i] = *reinterpret_cast<const uint4*>(
                    &sW[((wm * 2 + i) * 8 + ks) * ASTRIDE + lane * 4]);
#pragma unroll
            for (int j = 0; j < 4; j++)
                bf[j] = *reinterpret_cast<const uint2*>(
                    &sV[((wn * 4 + j) * 8 + ks) * BSTRIDE + lane * 2]);
#pragma unroll
            for (int i = 0; i < 2; i++)
#pragma unroll
                for (int j = 0; j < 4; j++)
                    mma_tf32(acc_o[i][j][0], acc_o[i][j][1], acc_o[i][j][2], acc_o[i][j][3],
                             af[i].x, af[i].y, af[i].z, af[i].w, bf[j].x, bf[j].y);
        }
        __syncthreads();
    }

    // finals: 1/l, m_fin; invert l in smem for O normalization
    if (tid < 128) {
        float inv = 1.0f / sl[tid];
        sl[tid] = inv;
        g_linv[(size_t)bh * S_ + row0 + tid] = inv;
        g_mfin[(size_t)bh * S_ + row0 + tid] = sm[tid];
    }
    __syncthreads();

    const int b = bh >> 4;
    const int h = bh & 15;
#pragma unroll
    for (int i = 0; i < 2; i++) {
        int r0 = wm * 32 + i * 16 + g;
        float il0 = sl[r0], il1 = sl[r0 + 8];
        int gr = row0 + r0;
#pragma unroll
        for (int j = 0; j < 4; j++) {
            int c0 = wn * 32 + j * 8 + qd * 2;
            float2 p0 = {acc_o[i][j][0] * il0, acc_o[i][j][1] * il0};
            float2 p1 = {acc_o[i][j][2] * il1, acc_o[i][j][3] * il1};
            size_t a0 = (((size_t)b * S_ + gr) * H_ + h) * HD_ + c0;
            size_t a1 = (((size_t)b * S_ + gr + 8) * H_ + h) * HD_ + c0;
            *reinterpret_cast<float2*>(&og[a0]) = p0;
            *reinterpret_cast<float2*>(&og[a1]) = p1;
        }
    }
}

// ---------------- weight rescale: w *= exp(m_kb - m_fin) / l ----------------
__global__ void __launch_bounds__(256)
rescale_kernel(float* __restrict__ w) {
    const size_t row = blockIdx.x; // B*H*S rows
    __shared__ float sfac[NKB_];
    const int tid = threadIdx.x;
    if (tid < NKB_)
        sfac[tid] = __expf(g_mkb[row * NKB_ + tid] - g_mfin[row]) * g_linv[row];
    __syncthreads();
    float* d = w + row * S_;
    float4 a = *reinterpret_cast<const float4*>(d + tid * 4);
    float4 b = *reinterpret_cast<const float4*>(d + 1024 + tid * 4);
    float f0 = sfac[tid >> 4];
    float f1 = sfac[16 + (tid >> 4)];
    a.x *= f0; a.y *= f0; a.z *= f0; a.w *= f0;
    b.x *= f1; b.y *= f1; b.z *= f1; b.w *= f1;
    *reinterpret_cast<float4*>(d + tid * 4) = a;
    *reinterpret_cast<float4*>(d + 1024 + tid * 4) = b;
}

// ---------------- launch ----------------
extern "C" void kernel_launch(void* const* d_in, const int* in_sizes, int n_in,
                              void* d_out, int out_size) {
    const float* query = (const float*)d_in[0];
    const float* W_qkv = (const float*)d_in[1];
    const float* b_qkv = (const float*)d_in[2];
    const float* W_out = (const float*)d_in[3];
    const float* b_out = (const float*)d_in[4];
    float* out = (float*)d_out;

    const size_t OUT_ELEMS = (size_t)B_ * S_ * D_;
    const size_t ATT_ELEMS = (size_t)B_ * H_ * S_ * S_;

    float* scores_ptr = nullptr;
    cudaGetSymbolAddress((void**)&scores_ptr, g_scores);
    float* wdst = ((size_t)out_size >= OUT_ELEMS + ATT_ELEMS) ? (out + OUT_ELEMS)
                                                              : scores_ptr;

    float *qp, *kp, *vp, *ap;
    cudaGetSymbolAddress((void**)&qp, g_q);
    cudaGetSymbolAddress((void**)&kp, g_kT);
    cudaGetSymbolAddress((void**)&vp, g_v);
    cudaGetSymbolAddress((void**)&ap, g_attn);

    cudaFuncSetAttribute(fused_attn_kernel,
                         cudaFuncAttributeMaxDynamicSharedMemorySize, SMEM_ATTN_BYTES);

    // 1) QKV projection
    {
        dim3 grid(3 * D_ / 128, (B_ * S_) / 128, 1);
        EpiQKV epi{b_qkv};
        tgemm_kernel<128, 128, 64, 32, EpiQKV><<<grid, 256>>>(
            query, W_qkv, D_, D_, 3 * D_, 0LL, 0LL, epi);
    }

    // 2) single-pass fused attention (writes unnormalized weights)
    {
        dim3 grid(S_ / 128, B_ * H_);
        fused_attn_kernel<<<grid, 256, SMEM_ATTN_BYTES>>>(qp, kp, vp, wdst, ap);
    }

    // 3) normalize attention weights in gmem
    {
        rescale_kernel<<<B_ * H_ * S_, 256>>>(wdst);
    }

    // 4) out projection
    {
        dim3 grid(D_ / 128, (B_ * S_) / 128, 1);
        EpiOut epi{b_out, out};
        tgemm_kernel<128, 128, 64, 32, EpiOut><<<grid, 256>>>(
            ap, W_out, D_, D_, D_, 0LL, 0LL, epi);
    }
}

// round 7
// speedup vs baseline: 2.2756x; 1.0393x over previous
#include <cuda_runtime.h>
#include <cstdio>
#include <cstdint>

#define B_ 2
#define S_ 2048
#define D_ 1024
#define H_ 16
#define HD_ 64
#define NKB_ 32   // S_/64 key blocks

// ---------------- scratch (device globals; no allocation allowed) ----------------
__device__ float g_q[(size_t)B_ * H_ * S_ * HD_];     // [B,H,S,Hd]
__device__ float g_kT[(size_t)B_ * H_ * HD_ * S_];    // [B,H,Hd,S]
__device__ float g_v[(size_t)B_ * H_ * S_ * HD_];     // [B,H,S,Hd]
__device__ float g_attn[(size_t)B_ * S_ * D_];        // [B,S,D]
__device__ float g_scores[(size_t)B_ * H_ * S_ * S_]; // fallback weights buffer
__device__ float g_mkb[(size_t)B_ * H_ * S_ * NKB_];  // running max at each kb
__device__ float g_mfin[(size_t)B_ * H_ * S_];        // final max per row
__device__ float g_linv[(size_t)B_ * H_ * S_];        // 1/l per row

// ---------------- helpers ----------------
__device__ __forceinline__ uint32_t f2tf32(float x) {
    uint32_t u;
    asm("cvt.rna.tf32.f32 %0, %1;" : "=r"(u) : "f"(x));
    return u;
}

__device__ __forceinline__ void mma_tf32(float& c0, float& c1, float& c2, float& c3,
                                         uint32_t a0, uint32_t a1, uint32_t a2, uint32_t a3,
                                         uint32_t b0, uint32_t b1) {
    asm volatile(
        "mma.sync.aligned.m16n8k8.row.col.f32.tf32.tf32.f32 "
        "{%0,%1,%2,%3}, {%4,%5,%6,%7}, {%8,%9}, {%0,%1,%2,%3};"
        : "+f"(c0), "+f"(c1), "+f"(c2), "+f"(c3)
        : "r"(a0), "r"(a1), "r"(a2), "r"(a3), "r"(b0), "r"(b1));
}

// padded fragment-layout strides (words) to kill staging bank conflicts
#define ASTRIDE 132   // A-frag: 32 lanes x 4 slots = 128 + 4 pad
#define BSTRIDE 66    // B-frag: 32 lanes x 2 slots = 64 + 2 pad

// ---------------- epilogues for projection GEMMs ----------------
struct EpiQKV {
    const float* bias;
    __device__ __forceinline__ void operator()(int, int m, int n, float v) const {
        v += bias[n];
        int part = n >> 10;
        int rem = n & 1023;
        int h = rem >> 6;
        int d = rem & 63;
        int b = m >> 11;
        int s = m & 2047;
        size_t bh = (size_t)(b * H_ + h);
        if (part == 0)
            g_q[(bh * S_ + s) * HD_ + d] = v;
        else if (part == 1)
            g_kT[(bh * HD_ + d) * S_ + s] = v;
        else
            g_v[(bh * S_ + s) * HD_ + d] = v;
    }
};

struct EpiOut {
    const float* bias;
    float* out;
    __device__ __forceinline__ void operator()(int, int m, int n, float v) const {
        out[(size_t)m * D_ + n] = v + bias[n];
    }
};

// ---------------- tf32 GEMM: 2-stage smem double-buffer pipeline --------------
// Iteration i: STS(tile i+1 -> buf ^cur) + LDG(tile i+2 -> regs) issued BEFORE
// the MMA phase on buf[cur]; one __syncthreads per iteration. Staging (LSU/cvt)
// overlaps tensor work.
template <int BM, int BN, int WM, int WN, class Epi>
__global__ void __launch_bounds__(256, 2)
tgemm_kernel(const float* __restrict__ Aall, const float* __restrict__ Ball,
             int K, int lda, int ldb,
             long long strideA, long long strideB, Epi epi) {
    constexpr int BK = 32;
    constexpr int NWN = BN / WN;
    constexpr int MT = WM / 16;
    constexpr int NT = WN / 8;
    constexpr int A4 = BM * BK / 4 / 256;
    constexpr int B4 = BK * BN / 4 / 256;
    constexpr int AW = (BM / 16) * 4 * ASTRIDE;
    constexpr int BW = (BN / 8) * 4 * BSTRIDE;

    extern __shared__ uint32_t dsm[];

    const int bz = blockIdx.z;
    const float* A = Aall + (size_t)bz * strideA;
    const float* Bp = Ball + (size_t)bz * strideB;

    const int tid = threadIdx.x;
    const int lane = tid & 31;
    const int warp = tid >> 5;
    const int wm = warp / NWN;
    const int wn = warp % NWN;
    const int row0 = blockIdx.y * BM;
    const int col0 = blockIdx.x * BN;

    float acc[MT][NT][4];
#pragma unroll
    for (int i = 0; i < MT; i++)
#pragma unroll
        for (int j = 0; j < NT; j++)
#pragma unroll
            for (int v = 0; v < 4; v++) acc[i][j][v] = 0.f;

    float4 pa[A4], pb[B4];

    auto loadAB = [&](int k0) {
#pragma unroll
        for (int it = 0; it < A4; ++it) {
            int idx = tid + it * 256;
            int r = idx >> 3, c4 = (idx & 7) << 2;
            pa[it] = *reinterpret_cast<const float4*>(
                &A[(size_t)(row0 + r) * lda + k0 + c4]);
        }
#pragma unroll
        for (int it = 0; it < B4; ++it) {
            int idx = tid + it * 256;
            int r = idx / (BN / 4), c4 = (idx % (BN / 4)) << 2;
            pb[it] = *reinterpret_cast<const float4*>(
                &Bp[(size_t)(k0 + r) * ldb + col0 + c4]);
        }
    };

    auto stageAB = [&](uint32_t* sA, uint32_t* sB) {
#pragma unroll
        for (int it = 0; it < A4; ++it) {
            int idx = tid + it * 256;
            int r = idx >> 3, c4 = (idx & 7) << 2;
            int mt = r >> 4, rw = r & 15;
            float vv[4] = {pa[it].x, pa[it].y, pa[it].z, pa[it].w};
#pragma unroll
            for (int j = 0; j < 4; j++) {
                int c = c4 + j;
                int ks = c >> 3, ci = c & 7;
                int ln = ((rw & 7) << 2) | (ci & 3);
                int slot = (rw >> 3) | ((ci >> 2) << 1);
                sA[((mt << 2) + ks) * ASTRIDE + ln * 4 + slot] = f2tf32(vv[j]);
            }
        }
#pragma unroll
        for (int it = 0; it < B4; ++it) {
            int idx = tid + it * 256;
            int r = idx / (BN / 4), c4 = (idx % (BN / 4)) << 2;
            int ks = r >> 3, rw = r & 7;
            float vv[4] = {pb[it].x, pb[it].y, pb[it].z, pb[it].w};
#pragma unroll
            for (int j = 0; j < 4; j++) {
                int n = c4 + j;
                int nt = n >> 3, ci = n & 7;
                int ln = (ci << 2) | (rw & 3);
                int slot = rw >> 2;
                sB[((nt << 2) + ks) * BSTRIDE + ln * 2 + slot] = f2tf32(vv[j]);
            }
        }
    };

    // prologue: tile0 -> buf0; prefetch tile1 regs
    loadAB(0);
    stageAB(dsm, dsm + AW);
    if (BK < K) loadAB(BK);
    __syncthreads();

    for (int k0 = 0; k0 < K; k0 += BK) {
        const int cur = (k0 / BK) & 1;
        uint32_t* cA = cur ? (dsm + AW + BW) : dsm;
        uint32_t* cB = cur ? (dsm + AW + BW + AW) : (dsm + AW);
        uint32_t* nA = cur ? dsm : (dsm + AW + BW);
        uint32_t* nB = cur ? (dsm + AW) : (dsm + AW + BW + AW);

        if (k0 + BK < K) stageAB(nA, nB);       // STS overlaps MMAs below
        if (k0 + 2 * BK < K) loadAB(k0 + 2 * BK);

#pragma unroll
        for (int ks = 0; ks < 4; ks++) {
            uint4 af[MT];
            uint2 bf[NT];
#pragma unroll
            for (int i = 0; i < MT; i++)
                af[i] = *reinterpret_cast<const uint4*>(
                    &cA[((wm * MT + i) * 4 + ks) * ASTRIDE + lane * 4]);
#pragma unroll
            for (int j = 0; j < NT; j++)
                bf[j] = *reinterpret_cast<const uint2*>(
                    &cB[((wn * NT + j) * 4 + ks) * BSTRIDE + lane * 2]);
#pragma unroll
            for (int i = 0; i < MT; i++)
#pragma unroll
                for (int j = 0; j < NT; j++)
                    mma_tf32(acc[i][j][0], acc[i][j][1], acc[i][j][2], acc[i][j][3],
                             af[i].x, af[i].y, af[i].z, af[i].w, bf[j].x, bf[j].y);
        }
        __syncthreads();
    }

#pragma unroll
    for (int i = 0; i < MT; i++) {
        int m0 = row0 + wm * WM + i * 16 + (lane >> 2);
#pragma unroll
        for (int j = 0; j < NT; j++) {
            int n0 = col0 + wn * WN + j * 8 + ((lane & 3) << 1);
            epi(bz, m0, n0, acc[i][j][0]);
            epi(bz, m0, n0 + 1, acc[i][j][1]);
            epi(bz, m0 + 8, n0, acc[i][j][2]);
            epi(bz, m0 + 8, n0 + 1, acc[i][j][3]);
        }
    }
}

// ---------------- single-pass flash attention (3 syncs/kb, staged overlap) ------
// smem words: sQ 8448 | sW 8448 | sK 4224 | sV 4224 | sm 128 | sl 128 |
//             (pad 128) | sredm 256 | sredl 256 = 26240 words = 104960 B
#define SMEM_ATTN_BYTES 104960
__global__ void __launch_bounds__(256, 2)
fused_attn_kernel(const float* __restrict__ qg, const float* __restrict__ kTg,
                  const float* __restrict__ vg, float* __restrict__ wout,
                  float* __restrict__ og) {
    extern __shared__ uint32_t smem[];
    uint32_t* sQ = smem;
    uint32_t* sW = smem + 8448;
    uint32_t* sK = smem + 16896;
    uint32_t* sV = smem + 21120;
    float* sm = (float*)(smem + 25344);
    float* sl = (float*)(smem + 25472);
    float* sredm = (float*)(smem + 25728);
    float* sredl = (float*)(smem + 25984);

    const int tid = threadIdx.x;
    const int lane = tid & 31;
    const int warp = tid >> 5;
    const int wm = warp >> 1;
    const int wn = warp & 1;
    const int g = lane >> 2;
    const int qd = lane & 3;
    const int row0 = blockIdx.x * 128;
    const int bh = blockIdx.y;

    const float* Q = qg + (size_t)bh * S_ * HD_;
    const float* KT = kTg + (size_t)bh * HD_ * S_;
    const float* V = vg + (size_t)bh * S_ * HD_;

    auto stageK = [&](int col0k) {
#pragma unroll
        for (int it = 0; it < 4; it++) {
            int idx = tid + it * 256;
            int r = idx >> 4, c4 = (idx & 15) << 2;
            float4 val = *reinterpret_cast<const float4*>(&KT[(size_t)r * S_ + col0k + c4]);
            int ks = r >> 3, rw = r & 7;
            float vv[4] = {val.x, val.y, val.z, val.w};
#pragma unroll
            for (int j = 0; j < 4; j++) {
                int n = c4 + j, nt = n >> 3, ci = n & 7;
                int ln = (ci << 2) | (rw & 3);
                int slot = rw >> 2;
                sK[((nt << 3) + ks) * BSTRIDE + ln * 2 + slot] = f2tf32(vv[j]);
            }
        }
    };
    auto stageV = [&](int col0k) {
#pragma unroll
        for (int it = 0; it < 4; it++) {
            int idx = tid + it * 256;
            int r = idx >> 4, c4 = (idx & 15) << 2;
            float4 val = *reinterpret_cast<const float4*>(&V[(size_t)(col0k + r) * HD_ + c4]);
            int ks = r >> 3, rw = r & 7;
            float vv[4] = {val.x, val.y, val.z, val.w};
#pragma unroll
            for (int j = 0; j < 4; j++) {
                int n = c4 + j, nt = n >> 3, ci = n & 7;
                int ln = (ci << 2) | (rw & 3);
                int slot = rw >> 2;
                sV[((nt << 3) + ks) * BSTRIDE + ln * 2 + slot] = f2tf32(vv[j]);
            }
        }
    };

    // stage Q once (pre-scaled by 1/8)
#pragma unroll
    for (int it = 0; it < 8; it++) {
        int idx = tid + it * 256;
        int r = idx >> 4, c4 = (idx & 15) << 2;
        float4 val = *reinterpret_cast<const float4*>(&Q[(size_t)(row0 + r) * HD_ + c4]);
        int mt = r >> 4, rw = r & 15;
        float vv[4] = {val.x, val.y, val.z, val.w};
#pragma unroll
        for (int j = 0; j < 4; j++) {
            int c = c4 + j, ks = c >> 3, ci = c & 7;
            int ln = ((rw & 7) << 2) | (ci & 3);
            int slot = (rw >> 3) | ((ci >> 2) << 1);
            sQ[((mt << 3) + ks) * ASTRIDE + ln * 4 + slot] = f2tf32(vv[j] * 0.125f);
        }
    }
    if (tid < 128) { sm[tid] = -1e30f; sl[tid] = 0.f; }
    stageK(0);
    stageV(0);

    float acc_o[2][4][4];
#pragma unroll
    for (int i = 0; i < 2; i++)
#pragma unroll
        for (int j = 0; j < 4; j++)
#pragma unroll
            for (int v = 0; v < 4; v++) acc_o[i][j][v] = 0.f;
    __syncthreads();

    for (int kb = 0; kb < NKB_; kb++) {
        const int col0k = kb * 64;

        // ---- S = Q @ K^T (128x64) ----
        float sacc[2][4][4];
#pragma unroll
        for (int i = 0; i < 2; i++)
#pragma unroll
            for (int j = 0; j < 4; j++)
#pragma unroll
                for (int v = 0; v < 4; v++) sacc[i][j][v] = 0.f;
#pragma unroll
        for (int ks = 0; ks < 8; ks++) {
            uint4 af[2];
            uint2 bf[4];
#pragma unroll
            for (int i = 0; i < 2; i++)
                af[i] = *reinterpret_cast<const uint4*>(
                    &sQ[((wm * 2 + i) * 8 + ks) * ASTRIDE + lane * 4]);
#pragma unroll
            for (int j = 0; j < 4; j++)
                bf[j] = *reinterpret_cast<const uint2*>(
                    &sK[((wn * 4 + j) * 8 + ks) * BSTRIDE + lane * 2]);
#pragma unroll
            for (int i = 0; i < 2; i++)
#pragma unroll
                for (int j = 0; j < 4; j++)
                    mma_tf32(sacc[i][j][0], sacc[i][j][1], sacc[i][j][2], sacc[i][j][3],
                             af[i].x, af[i].y, af[i].z, af[i].w, bf[j].x, bf[j].y);
        }

        // ---- block row-max -> sredm ----
#pragma unroll
        for (int i = 0; i < 2; i++) {
            int r0 = wm * 32 + i * 16 + g;
            float mx0 = -1e30f, mx1 = -1e30f;
#pragma unroll
            for (int j = 0; j < 4; j++) {
                mx0 = fmaxf(mx0, fmaxf(sacc[i][j][0], sacc[i][j][1]));
                mx1 = fmaxf(mx1, fmaxf(sacc[i][j][2], sacc[i][j][3]));
            }
            mx0 = fmaxf(mx0, __shfl_xor_sync(0xffffffffu, mx0, 1));
            mx0 = fmaxf(mx0, __shfl_xor_sync(0xffffffffu, mx0, 2));
            mx1 = fmaxf(mx1, __shfl_xor_sync(0xffffffffu, mx1, 1));
            mx1 = fmaxf(mx1, __shfl_xor_sync(0xffffffffu, mx1, 2));
            if (qd == 0) {
                sredm[wn * 128 + r0] = mx0;
                sredm[wn * 128 + r0 + 8] = mx1;
            }
        }
        __syncthreads();   // sync1: sredm ready; also orders V-staging(kb) done

        // ---- p-phase: per-thread m_new/alpha; p -> wout + sW; sredl partials ----
#pragma unroll
        for (int i = 0; i < 2; i++) {
            int r0 = wm * 32 + i * 16 + g;
            float mo0 = sm[r0], mo1 = sm[r0 + 8];
            float mn0 = fmaxf(mo0, fmaxf(sredm[r0], sredm[128 + r0]));
            float mn1 = fmaxf(mo1, fmaxf(sredm[r0 + 8], sredm[128 + r0 + 8]));
            float a0 = __expf(mo0 - mn0), a1 = __expf(mo1 - mn1);
            float s0 = 0.f, s1 = 0.f;
#pragma unroll
            for (int j = 0; j < 4; j++) {
                int c0 = wn * 32 + j * 8 + qd * 2;
                float p00 = __expf(sacc[i][j][0] - mn0);
                float p01 = __expf(sacc[i][j][1] - mn0);
                float p10 = __expf(sacc[i][j][2] - mn1);
                float p11 = __expf(sacc[i][j][3] - mn1);
                s0 += p00 + p01;
                s1 += p10 + p11;
                size_t base = ((size_t)bh * S_ + row0 + r0) * S_ + col0k + c0;
                float2 q0 = {p00, p01};
                float2 q1 = {p10, p11};
                *reinterpret_cast<float2*>(&wout[base]) = q0;
                *reinterpret_cast<float2*>(&wout[base + (size_t)8 * S_]) = q1;
                {
                    int rr = r0, rw2 = rr & 15, mt = rr >> 4;
                    int c = c0, ks = c >> 3, ci = c & 7;
                    int ln = ((rw2 & 7) << 2) | (ci & 3);
                    int slot = (rw2 >> 3) | ((ci >> 2) << 1);
                    sW[((mt << 3) + ks) * ASTRIDE + ln * 4 + slot] = f2tf32(p00);
                    ci = (c + 1) & 7;
                    ln = ((rw2 & 7) << 2) | (ci & 3);
                    slot = (rw2 >> 3) | ((ci >> 2) << 1);
                    sW[((mt << 3) + ks) * ASTRIDE + ln * 4 + slot] = f2tf32(p01);
                    rr = r0 + 8; rw2 = rr & 15; mt = rr >> 4;
                    ci = c & 7;
                    ln = ((rw2 & 7) << 2) | (ci & 3);
                    slot = (rw2 >> 3) | ((ci >> 2) << 1);
                    sW[((mt << 3) + ks) * ASTRIDE + ln * 4 + slot] = f2tf32(p10);
                    ci = (c + 1) & 7;
                    ln = ((rw2 & 7) << 2) | (ci & 3);
                    slot = (rw2 >> 3) | ((ci >> 2) << 1);
                    sW[((mt << 3) + ks) * ASTRIDE + ln * 4 + slot] = f2tf32(p11);
                }
                acc_o[i][j][0] *= a0; acc_o[i][j][1] *= a0;
                acc_o[i][j][2] *= a1; acc_o[i][j][3] *= a1;
            }
            s0 += __shfl_xor_sync(0xffffffffu, s0, 1);
            s0 += __shfl_xor_sync(0xffffffffu, s0, 2);
            s1 += __shfl_xor_sync(0xffffffffu, s1, 1);
            s1 += __shfl_xor_sync(0xffffffffu, s1, 2);
            if (qd == 0) {
                sredl[wn * 128 + r0] = s0;
                sredl[wn * 128 + r0 + 8] = s1;
            }
        }
        __syncthreads();   // sync2: sW + sredl ready; sK free for restage

        // ---- l/m update (tid<128) ----
        if (tid < 128) {
            float mo = sm[tid];
            float mn = fmaxf(mo, fmaxf(sredm[tid], sredm[128 + tid]));
            sl[tid] = sl[tid] * __expf(mo - mn) + sredl[tid] + sredl[128 + tid];
            sm[tid] = mn;
            g_mkb[((size_t)bh * S_ + row0 + tid) * NKB_ + kb] = mn;
        }

        // ---- K staging for next block (overlaps AV tensor work) ----
        if (kb + 1 < NKB_) stageK(col0k + 64);

        // ---- O += p @ V ----
#pragma unroll
        for (int ks = 0; ks < 8; ks++) {
            uint4 af[2];
            uint2 bf[4];
#pragma unroll
            for (int i = 0; i < 2; i++)
                af[i] = *reinterpret_cast<const uint4*>(
                    &sW[((wm * 2 + i) * 8 + ks) * ASTRIDE + lane * 4]);
#pragma unroll
            for (int j = 0; j < 4; j++)
                bf[j] = *reinterpret_cast<const uint2*>(
                    &sV[((wn * 4 + j) * 8 + ks) * BSTRIDE + lane * 2]);
#pragma unroll
            for (int i = 0; i < 2; i++)
#pragma unroll
                for (int j = 0; j < 4; j++)
                    mma_tf32(acc_o[i][j][0], acc_o[i][j][1], acc_o[i][j][2], acc_o[i][j][3],
                             af[i].x, af[i].y, af[i].z, af[i].w, bf[j].x, bf[j].y);
        }
        __syncthreads();   // sync3: sW/ sV free

        // ---- V staging for next block (overlaps next S-MMA) ----
        if (kb + 1 < NKB_) stageV(col0k + 64);
    }

    // finals
    if (tid < 128) {
        float inv = 1.0f / sl[tid];
        sl[tid] = inv;
        g_linv[(size_t)bh * S_ + row0 + tid] = inv;
        g_mfin[(size_t)bh * S_ + row0 + tid] = sm[tid];
    }
    __syncthreads();

    const int b = bh >> 4;
    const int h = bh & 15;
#pragma unroll
    for (int i = 0; i < 2; i++) {
        int r0 = wm * 32 + i * 16 + g;
        float il0 = sl[r0], il1 = sl[r0 + 8];
        int gr = row0 + r0;
#pragma unroll
        for (int j = 0; j < 4; j++) {
            int c0 = wn * 32 + j * 8 + qd * 2;
            float2 p0 = {acc_o[i][j][0] * il0, acc_o[i][j][1] * il0};
            float2 p1 = {acc_o[i][j][2] * il1, acc_o[i][j][3] * il1};
            size_t a0 = (((size_t)b * S_ + gr) * H_ + h) * HD_ + c0;
            size_t a1 = (((size_t)b * S_ + gr + 8) * H_ + h) * HD_ + c0;
            *reinterpret_cast<float2*>(&og[a0]) = p0;
            *reinterpret_cast<float2*>(&og[a1]) = p1;
        }
    }
}

// ---------------- weight rescale: w *= exp(m_kb - m_fin) / l ----------------
__global__ void __launch_bounds__(256)
rescale_kernel(float* __restrict__ w) {
    const size_t row = blockIdx.x; // B*H*S rows
    __shared__ float sfac[NKB_];
    const int tid = threadIdx.x;
    if (tid < NKB_)
        sfac[tid] = __expf(g_mkb[row * NKB_ + tid] - g_mfin[row]) * g_linv[row];
    __syncthreads();
    float* d = w + row * S_;
    float4 a = *reinterpret_cast<const float4*>(d + tid * 4);
    float4 b = *reinterpret_cast<const float4*>(d + 1024 + tid * 4);
    float f0 = sfac[tid >> 4];
    float f1 = sfac[16 + (tid >> 4)];
    a.x *= f0; a.y *= f0; a.z *= f0; a.w *= f0;
    b.x *= f1; b.y *= f1; b.z *= f1; b.w *= f1;
    *reinterpret_cast<float4*>(d + tid * 4) = a;
    *reinterpret_cast<float4*>(d + 1024 + tid * 4) = b;
}

// ---------------- launch ----------------
extern "C" void kernel_launch(void* const* d_in, const int* in_sizes, int n_in,
                              void* d_out, int out_size) {
    const float* query = (const float*)d_in[0];
    const float* W_qkv = (const float*)d_in[1];
    const float* b_qkv = (const float*)d_in[2];
    const float* W_out = (const float*)d_in[3];
    const float* b_out = (const float*)d_in[4];
    float* out = (float*)d_out;

    const size_t OUT_ELEMS = (size_t)B_ * S_ * D_;
    const size_t ATT_ELEMS = (size_t)B_ * H_ * S_ * S_;

    float* scores_ptr = nullptr;
    cudaGetSymbolAddress((void**)&scores_ptr, g_scores);
    float* wdst = ((size_t)out_size >= OUT_ELEMS + ATT_ELEMS) ? (out + OUT_ELEMS)
                                                              : scores_ptr;

    float *qp, *kp, *vp, *ap;
    cudaGetSymbolAddress((void**)&qp, g_q);
    cudaGetSymbolAddress((void**)&kp, g_kT);
    cudaGetSymbolAddress((void**)&vp, g_v);
    cudaGetSymbolAddress((void**)&ap, g_attn);

    // 2 buffers x (sA 4224 + sB 4224 words) = 67584 bytes for 128x128 tiles
    const int TG_SMEM = 2 * ((128 / 16) * 4 * 132 + (128 / 8) * 4 * 66) * 4;

    cudaFuncSetAttribute(fused_attn_kernel,
                         cudaFuncAttributeMaxDynamicSharedMemorySize, SMEM_ATTN_BYTES);
    cudaFuncSetAttribute(tgemm_kernel<128, 128, 64, 32, EpiQKV>,
                         cudaFuncAttributeMaxDynamicSharedMemorySize, TG_SMEM);
    cudaFuncSetAttribute(tgemm_kernel<128, 128, 64, 32, EpiOut>,
                         cudaFuncAttributeMaxDynamicSharedMemorySize, TG_SMEM);

    // 1) QKV projection
    {
        dim3 grid(3 * D_ / 128, (B_ * S_) / 128, 1);
        EpiQKV epi{b_qkv};
        tgemm_kernel<128, 128, 64, 32, EpiQKV><<<grid, 256, TG_SMEM>>>(
            query, W_qkv, D_, D_, 3 * D_, 0LL, 0LL, epi);
    }

    // 2) single-pass fused attention (writes unnormalized weights)
    {
        dim3 grid(S_ / 128, B_ * H_);
        fused_attn_kernel<<<grid, 256, SMEM_ATTN_BYTES>>>(qp, kp, vp, wdst, ap);
    }

    // 3) normalize attention weights in gmem
    {
        rescale_kernel<<<B_ * H_ * S_, 256>>>(wdst);
    }

    // 4) out projection
    {
        dim3 grid(D_ / 128, (B_ * S_) / 128, 1);
        EpiOut epi{b_out, out};
        tgemm_kernel<128, 128, 64, 32, EpiOut><<<grid, 256, TG_SMEM>>>(
            ap, W_out, D_, D_, D_, 0LL, 0LL, epi);
    }
}